// round 4
// baseline (speedup 1.0000x reference)
#include <cuda_runtime.h>
#include <cuda_bf16.h>
#include <cstdint>

#define B_ 4
#define N_ 8192
#define C_ 64
#define K_ 16
#define O_ 128
#define M_KEEP 24   // approx-filter margin (>=16)

// ---------------- scratch (no allocs allowed) ----------------
__device__ __align__(16) float         g_feats[B_ * N_ * C_];
__device__ __align__(16) float         g_xx[B_ * N_];
__device__ __align__(16) int           g_knn[B_ * N_ * K_];
__device__ __align__(16) __nv_bfloat16 g_hi[B_ * N_ * C_];
__device__ __align__(16) __nv_bfloat16 g_lo[B_ * N_ * C_];

typedef unsigned long long u64;

// ---------------- packed f32x2 helpers (sm_103a) ----------------
__device__ __forceinline__ u64 fma2(u64 a, u64 b, u64 c) {
    u64 d;
    asm("fma.rn.f32x2 %0, %1, %2, %3;" : "=l"(d) : "l"(a), "l"(b), "l"(c));
    return d;
}
__device__ __forceinline__ u64 add2(u64 a, u64 b) {
    u64 d;
    asm("add.rn.f32x2 %0, %1, %2;" : "=l"(d) : "l"(a), "l"(b));
    return d;
}
__device__ __forceinline__ float psum(u64 v) {
    return __uint_as_float((unsigned)v) + __uint_as_float((unsigned)(v >> 32));
}

__device__ __forceinline__ uint32_t smem_u32(const void* p) {
    uint32_t a;
    asm("{ .reg .u64 t; cvta.to.shared.u64 t, %1; cvt.u32.u64 %0, t; }" : "=r"(a) : "l"(p));
    return a;
}

// classic HMMA (baseline PTX, legal on compute_103)
__device__ __forceinline__ void mma_bf16(float* c, const unsigned* a, const unsigned* b) {
    asm volatile(
        "mma.sync.aligned.m16n8k16.row.col.f32.bf16.bf16.f32 "
        "{%0,%1,%2,%3}, {%4,%5,%6,%7}, {%8,%9}, {%0,%1,%2,%3};"
        : "+f"(c[0]), "+f"(c[1]), "+f"(c[2]), "+f"(c[3])
        : "r"(a[0]), "r"(a[1]), "r"(a[2]), "r"(a[3]), "r"(b[0]), "r"(b[1]));
}

__device__ __forceinline__ void cp_async16(uint32_t dst, const void* src) {
    asm volatile("cp.async.cg.shared.global [%0], [%1], 16;" :: "r"(dst), "l"(src) : "memory");
}
__device__ __forceinline__ void cp_commit() {
    asm volatile("cp.async.commit_group;" ::: "memory");
}
__device__ __forceinline__ void cp_wait1() {
    asm volatile("cp.async.wait_group 1;" ::: "memory");
}
__device__ __forceinline__ void cp_wait0() {
    asm volatile("cp.async.wait_group 0;" ::: "memory");
}

// ---------------- kernel 1: transpose, norms, bf16 hi/lo split ----------------
__global__ void __launch_bounds__(256) prep_kernel(const float* __restrict__ x) {
    int idx = blockIdx.x * 256 + threadIdx.x;      // 0 .. B*N-1
    int b = idx >> 13;
    int n = idx & (N_ - 1);
    const float* xb = x + (size_t)b * C_ * N_ + n;
    float v[C_];
    float acc = 0.f;
#pragma unroll
    for (int c = 0; c < C_; ++c) {
        float t = xb[(size_t)c * N_];
        v[c] = t;
        acc = fmaf(t, t, acc);
    }
    float4* fp = reinterpret_cast<float4*>(g_feats + (size_t)idx * C_);
#pragma unroll
    for (int i = 0; i < C_ / 4; ++i)
        fp[i] = make_float4(v[4 * i], v[4 * i + 1], v[4 * i + 2], v[4 * i + 3]);

    uint4* hq = reinterpret_cast<uint4*>(g_hi + (size_t)idx * C_);
    uint4* lq = reinterpret_cast<uint4*>(g_lo + (size_t)idx * C_);
#pragma unroll
    for (int g = 0; g < 8; ++g) {
        unsigned hp[4], lp[4];
#pragma unroll
        for (int i = 0; i < 4; ++i) {
            float a = v[8 * g + 2 * i], bb = v[8 * g + 2 * i + 1];
            __nv_bfloat16 ha = __float2bfloat16(a);
            __nv_bfloat16 hb = __float2bfloat16(bb);
            __nv_bfloat16 la = __float2bfloat16(a - __bfloat162float(ha));
            __nv_bfloat16 lb = __float2bfloat16(bb - __bfloat162float(hb));
            hp[i] = (unsigned)__bfloat16_as_ushort(ha) | ((unsigned)__bfloat16_as_ushort(hb) << 16);
            lp[i] = (unsigned)__bfloat16_as_ushort(la) | ((unsigned)__bfloat16_as_ushort(lb) << 16);
        }
        hq[g] = make_uint4(hp[0], hp[1], hp[2], hp[3]);
        lq[g] = make_uint4(lp[0], lp[1], lp[2], lp[3]);
    }
    g_xx[idx] = acc;
}

// ---------------- kernel 2: HMMA tensor-core KNN (filter) + exact rescore ----------------
// 256 threads = 8 warps; block computes 128 queries x all 8192 candidates.
// smem layout (bytes):
#define S_A     0                          // A hi (16K) + A lo (16K)
#define S_B     32768                      // 2 bufs x (hi 16K + lo 16K) = 64K
#define S_DIST  98304                      // 128 x 132 fp32 = 67584
#define S_CXX   165888                     // 2 x 128 fp32
#define S_MV    166912                     // 256 x M_KEEP fp32 = 24576
#define S_MI    (S_MV + 256 * M_KEEP * 4)  // 256 x M_KEEP int = 24576
#define KNN_SMEM (S_MI + 256 * M_KEEP * 4) // 216064

__global__ void __launch_bounds__(256, 1) knn_mma_kernel() {
    extern __shared__ char smem[];
    uint32_t sb = smem_u32(smem);
    const int t = threadIdx.x;
    const int w = t >> 5;                 // warp 0..7
    const int l = t & 31;
    const int b = blockIdx.y;
    const int q0 = blockIdx.x * 128;

    const int m0 = (w & 3) * 32;          // warp row base (queries)
    const int n0 = (w >> 2) * 64;         // warp col base (candidates)
    const int lrow = l >> 2;              // 0..7
    const int lc = l & 3;                 // 0..3
    const int swz = lrow << 2;            // B-tile XOR swizzle

    const __nv_bfloat16* hib = g_hi + (size_t)b * N_ * C_;
    const __nv_bfloat16* lob = g_lo + (size_t)b * N_ * C_;
    const float* xxb = g_xx + b * N_;

    float* s_dist = reinterpret_cast<float*>(smem + S_DIST);
    float* s_cxx  = reinterpret_cast<float*>(smem + S_CXX);
    float* s_mv   = reinterpret_cast<float*>(smem + S_MV);
    int*   s_mi   = reinterpret_cast<int*>(smem + S_MI);

    // ---- copy A tile (queries, hi+lo) plain row-major, 128B rows ----
    {
        const uint4* sh = reinterpret_cast<const uint4*>(hib + (size_t)q0 * C_);
        const uint4* sl = reinterpret_cast<const uint4*>(lob + (size_t)q0 * C_);
        uint4* dh = reinterpret_cast<uint4*>(smem + S_A);
        uint4* dl = reinterpret_cast<uint4*>(smem + S_A + 16384);
#pragma unroll
        for (int i = 0; i < 4; ++i) {
            dh[t + i * 256] = sh[t + i * 256];
            dl[t + i * 256] = sl[t + i * 256];
        }
    }

    // ---- issue cp.async for a B tile ----
    auto issue_b = [&](int tile, int buf) {
        const char* srcs[2] = { (const char*)(hib + (size_t)tile * 128 * C_),
                                (const char*)(lob + (size_t)tile * 128 * C_) };
#pragma unroll
        for (int half = 0; half < 2; ++half) {
            uint32_t base = sb + S_B + buf * 32768 + half * 16384;
#pragma unroll
            for (int i = 0; i < 4; ++i) {
                int cid = t + i * 256;               // 0..1023
                int n = cid >> 3, c = cid & 7;
                int cs = c ^ (n & 7);
                cp_async16(base + n * 128 + cs * 16, srcs[half] + (size_t)cid * 16);
            }
        }
        cp_commit();
    };
    issue_b(0, 0);

    // per-warp query norms for epilogue fold
    float qr0 = xxb[q0 + m0 + lrow];
    float qr1 = xxb[q0 + m0 + lrow + 8];
    float qr0b = xxb[q0 + m0 + 16 + lrow];
    float qr1b = xxb[q0 + m0 + 16 + lrow + 8];

    // candidate-norm prefetch for tile 0
    float cxxr = (t < 128) ? xxb[t] : 0.f;

    // init approx top-M lists
    float* mv = s_mv + t * M_KEEP;
    int*   mi = s_mi + t * M_KEEP;
#pragma unroll
    for (int i = 0; i < M_KEEP; ++i) { mv[i] = -3.4e38f; mi[i] = 0; }
    float thr = -3.4e38f;

    __syncthreads();   // A tile visible

    // ---- load persistent A fragments: af[split][mf][ks][4] ----
    unsigned af[2][2][4][4];
    {
        const unsigned* ab[2] = { reinterpret_cast<const unsigned*>(smem + S_A),
                                  reinterpret_cast<const unsigned*>(smem + S_A + 16384) };
#pragma unroll
        for (int s = 0; s < 2; ++s)
#pragma unroll
            for (int mf = 0; mf < 2; ++mf)
#pragma unroll
                for (int ks = 0; ks < 4; ++ks) {
                    int r = m0 + mf * 16 + lrow;
                    int wbase = r * 32 + ks * 8 + lc;
                    af[s][mf][ks][0] = ab[s][wbase];
                    af[s][mf][ks][1] = ab[s][wbase + 8 * 32];
                    af[s][mf][ks][2] = ab[s][wbase + 4];
                    af[s][mf][ks][3] = ab[s][wbase + 8 * 32 + 4];
                }
    }

    const int srow = t & 127;     // scan: query row
    const int shalf = t >> 7;     // scan: column half

    for (int tile = 0; tile < 64; ++tile) {
        int par = tile & 1;
        if (t < 128) s_cxx[par * 128 + t] = cxxr;
        if (tile + 1 < 64) {
            cxxr = (t < 128) ? xxb[(tile + 1) * 128 + t] : 0.f;
            issue_b(tile + 1, par ^ 1);
            cp_wait1();
        } else {
            cp_wait0();
        }
        __syncthreads();          // B(tile) + cxx visible

        // ---- MMA: acc[mf][nf][4] over 3 split-GEMMs x 4 k-steps ----
        float acc[2][8][4];
#pragma unroll
        for (int mf = 0; mf < 2; ++mf)
#pragma unroll
            for (int nf = 0; nf < 8; ++nf)
#pragma unroll
                for (int r = 0; r < 4; ++r) acc[mf][nf][r] = 0.f;

        const unsigned* bhi = reinterpret_cast<const unsigned*>(smem + S_B + par * 32768);
        const unsigned* blo = bhi + 16384 / 4;

#pragma unroll
        for (int s = 0; s < 3; ++s) {
            const int asel = (s == 2) ? 1 : 0;
            const unsigned* bp = (s == 1) ? blo : bhi;
#pragma unroll
            for (int ks = 0; ks < 4; ++ks) {
                unsigned bf[8][2];
#pragma unroll
                for (int nf = 0; nf < 8; ++nf) {
                    int nrow = n0 + nf * 8 + lrow;
                    bf[nf][0] = bp[nrow * 32 + ((ks * 8 + lc) ^ swz)];
                    bf[nf][1] = bp[nrow * 32 + ((ks * 8 + 4 + lc) ^ swz)];
                }
#pragma unroll
                for (int mf = 0; mf < 2; ++mf)
#pragma unroll
                    for (int nf = 0; nf < 8; ++nf)
                        mma_bf16(acc[mf][nf], af[asel][mf][ks], bf[nf]);
            }
        }

        // ---- epilogue: fold 2*inner - qxx - cxx, store to padded dist ----
#pragma unroll
        for (int mf = 0; mf < 2; ++mf) {
            float q0v = mf ? qr0b : qr0;
            float q1v = mf ? qr1b : qr1;
#pragma unroll
            for (int nf = 0; nf < 8; ++nf) {
                int col = n0 + nf * 8 + lc * 2;
                float cx0 = s_cxx[par * 128 + col];
                float cx1 = s_cxx[par * 128 + col + 1];
                int r0 = m0 + mf * 16 + lrow;
                float2 d0 = make_float2(2.f * acc[mf][nf][0] - q0v - cx0,
                                        2.f * acc[mf][nf][1] - q0v - cx1);
                float2 d1 = make_float2(2.f * acc[mf][nf][2] - q1v - cx0,
                                        2.f * acc[mf][nf][3] - q1v - cx1);
                *reinterpret_cast<float2*>(s_dist + r0 * 132 + col) = d0;
                *reinterpret_cast<float2*>(s_dist + (r0 + 8) * 132 + col) = d1;
            }
        }
        __syncthreads();          // dist complete

        // ---- scan: 2 threads per query, 64 cols each; keep approx top-M ----
        {
            const float4* dp = reinterpret_cast<const float4*>(s_dist + srow * 132 + shalf * 64);
            int cbase = tile * 128 + shalf * 64;
#pragma unroll 4
            for (int j = 0; j < 16; ++j) {
                float4 v = dp[j];
                float dv[4] = { v.x, v.y, v.z, v.w };
#pragma unroll
                for (int e = 0; e < 4; ++e) {
                    float d = dv[e];
                    if (d > thr) {
                        int jj = cbase + 4 * j + e;
                        int p = M_KEEP - 1;
                        while (p > 0 && mv[p - 1] < d) {
                            mv[p] = mv[p - 1];
                            mi[p] = mi[p - 1];
                            --p;
                        }
                        mv[p] = d;
                        mi[p] = jj;
                        thr = mv[M_KEEP - 1];
                    }
                }
            }
        }
        __syncthreads();          // scan done before next dist store
    }

    // ---- exact fp32 rescore of this thread's M_KEEP approx candidates ----
    {
        const float* fbf = g_feats + (size_t)b * N_ * C_;
        const u64* qp = reinterpret_cast<const u64*>(fbf + (size_t)(q0 + srow) * C_);
        u64 qv2[32];
#pragma unroll
        for (int i = 0; i < 32; ++i) qv2[i] = qp[i];
        float qxxe = xxb[q0 + srow];
#pragma unroll 1
        for (int i = 0; i < M_KEEP; ++i) {
            int idx = mi[i];
            const u64* cp = reinterpret_cast<const u64*>(fbf + (size_t)idx * C_);
            u64 a0 = 0, a1 = 0, a2 = 0, a3 = 0;
#pragma unroll
            for (int j = 0; j < 8; ++j) {
                a0 = fma2(qv2[4 * j + 0], cp[4 * j + 0], a0);
                a1 = fma2(qv2[4 * j + 1], cp[4 * j + 1], a1);
                a2 = fma2(qv2[4 * j + 2], cp[4 * j + 2], a2);
                a3 = fma2(qv2[4 * j + 3], cp[4 * j + 3], a3);
            }
            float inner = psum(add2(add2(a0, a1), add2(a2, a3)));
            mv[i] = 2.f * inner - qxxe - xxb[idx];
        }
        // insertion sort by (val desc, idx asc) — nearly sorted already
#pragma unroll 1
        for (int i = 1; i < M_KEEP; ++i) {
            float v = mv[i];
            int ix = mi[i];
            int p = i;
            while (p > 0 && (mv[p - 1] < v || (mv[p - 1] == v && mi[p - 1] > ix))) {
                mv[p] = mv[p - 1];
                mi[p] = mi[p - 1];
                --p;
            }
            mv[p] = v;
            mi[p] = ix;
        }
    }
    __syncthreads();

    // ---- merge the two exact half-lists per query, write top-16 ----
    if (t < 128) {
        float* v1 = s_mv + t * M_KEEP;
        int*   i1 = s_mi + t * M_KEEP;
        float* v2 = s_mv + (t + 128) * M_KEEP;
        int*   i2 = s_mi + (t + 128) * M_KEEP;
        int p1 = 0, p2 = 0;
        int* og = g_knn + (size_t)(b * N_ + q0 + t) * K_;
#pragma unroll
        for (int s = 0; s < 16; ++s) {
            float a = v1[p1], bb = v2[p2];
            bool ta = (a > bb) || (a == bb && i1[p1] < i2[p2]);
            og[s] = ta ? i1[p1] : i2[p2];
            if (ta) ++p1; else ++p2;
        }
    }
}

// ---------------- kernel 3: edge conv + max pool ----------------
#define CT  128   // threads = output channels
#define PPB 64    // points per block

__device__ __forceinline__ void cv_issue(const float* fb, const int* s_nidx,
                                         int p0, int pl, int t,
                                         float4* rn, float4* rx) {
#pragma unroll
    for (int s = 0; s < 3; ++s) {
        if (s == 2 && t >= 16) continue;
        int cid = t + s * CT;
        int r = cid >> 4, c4 = cid & 15;
        const float4* xrow = reinterpret_cast<const float4*>(fb + (size_t)(p0 + pl) * C_);
        if (r < 16) {
            int nj = s_nidx[pl * K_ + r];
            rn[s] = reinterpret_cast<const float4*>(fb + (size_t)nj * C_)[c4];
            rx[s] = xrow[c4];
        } else {
            rn[s] = xrow[c4];
        }
    }
}

__device__ __forceinline__ void cv_commit(float4* buf, int t,
                                          const float4* rn, const float4* rx) {
#pragma unroll
    for (int s = 0; s < 3; ++s) {
        if (s == 2 && t >= 16) continue;
        int cid = t + s * CT;
        int r = cid >> 4, c4 = cid & 15;
        float4 v = rn[s];
        if (r < 16) { v.x -= rx[s].x; v.y -= rx[s].y; v.z -= rx[s].z; v.w -= rx[s].w; }
        buf[r * 16 + c4] = v;
    }
}

__global__ void __launch_bounds__(CT) conv_kernel(const float* __restrict__ W,
                                                  const float* __restrict__ bias,
                                                  float* __restrict__ out) {
    __shared__ float4 sbuf[2][17 * 16];
    __shared__ int s_nidx[PPB * K_];

    int b = blockIdx.y;
    int p0 = blockIdx.x * PPB;
    int t = threadIdx.x;
    const float* fb = g_feats + (size_t)b * N_ * C_;

    u64 w2[64];
    {
        const u64* wp = reinterpret_cast<const u64*>(W + (size_t)t * 2 * C_);
#pragma unroll
        for (int i = 0; i < 64; ++i) w2[i] = wp[i];
    }
    float bo = bias[t];

    for (int i = t; i < PPB * K_; i += CT)
        s_nidx[i] = g_knn[(size_t)(b * N_ + p0) * K_ + i];
    __syncthreads();

    float4 rn[3], rx[3];
    cv_issue(fb, s_nidx, p0, 0, t, rn, rx);

    for (int pl = 0; pl < PPB; ++pl) {
        float4* buf = sbuf[pl & 1];
        cv_commit(buf, t, rn, rx);
        __syncthreads();
        if (pl + 1 < PPB) cv_issue(fb, s_nidx, p0, pl + 1, t, rn, rx);

        const ulonglong2* base = reinterpret_cast<const ulonglong2*>(buf);

        u64 a0 = 0, a1 = 0;
#pragma unroll
        for (int i = 0; i < 16; ++i) {
            ulonglong2 u = base[16 * 16 + i];
            a0 = fma2(w2[2 * i], u.x, a0);
            a1 = fma2(w2[2 * i + 1], u.y, a1);
        }
        float aterm = psum(add2(a0, a1));

        float m = -3.4e38f;
#pragma unroll
        for (int k = 0; k < 16; ++k) {
            u64 c0 = 0, c1 = 0;
#pragma unroll
            for (int i = 0; i < 16; ++i) {
                ulonglong2 u = base[k * 16 + i];
                c0 = fma2(w2[32 + 2 * i], u.x, c0);
                c1 = fma2(w2[33 + 2 * i], u.y, c1);
            }
            float tk = psum(add2(c0, c1));
            m = fmaxf(m, tk);
        }

        out[(size_t)(b * O_ + t) * N_ + p0 + pl] = aterm + m + bo;
    }
}

// ---------------- launch ----------------
extern "C" void kernel_launch(void* const* d_in, const int* in_sizes, int n_in,
                              void* d_out, int out_size) {
    (void)in_sizes; (void)n_in; (void)out_size;
    const float* x    = (const float*)d_in[0];   // (4, 64, 8192, 1)
    const float* W    = (const float*)d_in[1];   // (128, 128)
    const float* bias = (const float*)d_in[2];   // (128,)
    float* out = (float*)d_out;                  // (4, 128, 8192, 1)

    cudaFuncSetAttribute(knn_mma_kernel, cudaFuncAttributeMaxDynamicSharedMemorySize, KNN_SMEM);

    prep_kernel<<<(B_ * N_) / 256, 256>>>(x);
    knn_mma_kernel<<<dim3(N_ / 128, B_), 256, KNN_SMEM>>>();
    conv_kernel<<<dim3(N_ / PPB, B_), CT>>>(W, bias, out);
}

// round 5
// speedup vs baseline: 1.1942x; 1.1942x over previous
#include <cuda_runtime.h>
#include <cuda_bf16.h>
#include <cstdint>

#define B_ 4
#define N_ 8192
#define C_ 64
#define K_ 16
#define O_ 128

#define CH 4                       // candidate chunks per query
#define QT 256                     // threads = queries per CTA
#define CTILE 128                  // candidates per smem tile
#define CCHUNK (N_ / CH)           // 2048
#define NTILES (CCHUNK / CTILE)    // 16

// ---------------- scratch (no allocs allowed) ----------------
__device__ __align__(16) float g_feats[B_ * N_ * C_];
__device__ __align__(16) float g_xx[B_ * N_];
__device__ __align__(16) int   g_knn[B_ * N_ * K_];
__device__ __align__(16) float g_pval[B_ * CH * N_ * K_];   // partial top-16 values
__device__ __align__(16) int   g_pidx[B_ * CH * N_ * K_];   // partial top-16 indices

typedef unsigned long long u64;

// ---------------- packed f32x2 helpers (sm_103a) ----------------
__device__ __forceinline__ u64 fma2(u64 a, u64 b, u64 c) {
    u64 d;
    asm("fma.rn.f32x2 %0, %1, %2, %3;" : "=l"(d) : "l"(a), "l"(b), "l"(c));
    return d;
}
__device__ __forceinline__ u64 add2(u64 a, u64 b) {
    u64 d;
    asm("add.rn.f32x2 %0, %1, %2;" : "=l"(d) : "l"(a), "l"(b));
    return d;
}
__device__ __forceinline__ float psum(u64 v) {
    return __uint_as_float((unsigned)v) + __uint_as_float((unsigned)(v >> 32));
}
__device__ __forceinline__ uint32_t smem_u32(const void* p) {
    uint32_t a;
    asm("{ .reg .u64 t; cvta.to.shared.u64 t, %1; cvt.u32.u64 %0, t; }" : "=r"(a) : "l"(p));
    return a;
}
__device__ __forceinline__ void cp_async16(uint32_t dst, const void* src) {
    asm volatile("cp.async.cg.shared.global [%0], [%1], 16;" :: "r"(dst), "l"(src) : "memory");
}
__device__ __forceinline__ void cp_commit() {
    asm volatile("cp.async.commit_group;" ::: "memory");
}
__device__ __forceinline__ void cp_wait1() {
    asm volatile("cp.async.wait_group 1;" ::: "memory");
}
__device__ __forceinline__ void cp_wait0() {
    asm volatile("cp.async.wait_group 0;" ::: "memory");
}

// ---------------- kernel 1: transpose x -> feats, compute ||x||^2 ----------------
__global__ void __launch_bounds__(256) prep_kernel(const float* __restrict__ x) {
    int idx = blockIdx.x * 256 + threadIdx.x;      // 0 .. B*N-1
    int b = idx >> 13;
    int n = idx & (N_ - 1);
    const float* xb = x + (size_t)b * C_ * N_ + n;
    float v[C_];
    float acc = 0.f;
#pragma unroll
    for (int c = 0; c < C_; ++c) {
        float t = xb[(size_t)c * N_];              // coalesced across threads
        v[c] = t;
        acc = fmaf(t, t, acc);
    }
    float4* fp = reinterpret_cast<float4*>(g_feats + (size_t)idx * C_);
#pragma unroll
    for (int i = 0; i < C_ / 4; ++i)
        fp[i] = make_float4(v[4 * i], v[4 * i + 1], v[4 * i + 2], v[4 * i + 3]);
    g_xx[idx] = acc;
}

// ---------------- kernel 2: exact fp32 KNN, FFMA2-pipe optimized ----------------
// Grid (32, CH, B_): 256 queries x 2048 candidates per CTA.
// smem layout (bytes):
#define KS_TILE 0                         // 2 x 32768 candidate tiles
#define KS_CXX  65536                     // 2 x 128 floats
#define KS_MV   66560                     // 256 x 16 fp32
#define KS_MI   82944                     // 256 x 16 int
#define KNN_SMEM 99328

__global__ void __launch_bounds__(QT, 2) knn_kernel() {
    extern __shared__ char smem[];
    uint32_t sb = smem_u32(smem);
    const int t = threadIdx.x;
    const int b = blockIdx.z;
    const int ch = blockIdx.y;
    const int q = blockIdx.x * QT + t;
    const int c0 = ch * CCHUNK;

    const float* fb = g_feats + (size_t)b * N_ * C_;
    const float* xxb = g_xx + b * N_;

    float* s_cxx = reinterpret_cast<float*>(smem + KS_CXX);
    float* mv = reinterpret_cast<float*>(smem + KS_MV) + t * 16;
    int*   mi = reinterpret_cast<int*>(smem + KS_MI) + t * 16;

    // query row in registers (64 regs)
    u64 qv[32];
    {
        const u64* qp = reinterpret_cast<const u64*>(fb + (size_t)q * C_);
#pragma unroll
        for (int i = 0; i < 32; ++i) qv[i] = qp[i];
    }
    const float qxx = xxb[q];
#pragma unroll
    for (int i = 0; i < 16; ++i) { mv[i] = -3.4e38f; mi[i] = 0; }
    float thr = -3.4e38f;

    // cp.async tile loader: 128 rows x 256 B = 2048 x 16B chunks, 8 per thread
    auto issue = [&](int tile, int buf) {
        const char* src = reinterpret_cast<const char*>(fb + (size_t)(c0 + tile * CTILE) * C_);
        uint32_t dst = sb + KS_TILE + buf * 32768;
#pragma unroll
        for (int i = 0; i < 8; ++i) {
            int chunk = t + i * QT;
            cp_async16(dst + chunk * 16, src + (size_t)chunk * 16);
        }
        cp_commit();
        if (t < CTILE) s_cxx[buf * CTILE + t] = xxb[c0 + tile * CTILE + t];
    };
    issue(0, 0);

    for (int tile = 0; tile < NTILES; ++tile) {
        const int buf = tile & 1;
        if (tile + 1 < NTILES) { issue(tile + 1, buf ^ 1); cp_wait1(); }
        else                   { cp_wait0(); }
        __syncthreads();                    // tile + cxx visible

        const ulonglong2* tb = reinterpret_cast<const ulonglong2*>(smem + KS_TILE + buf * 32768);
        const float* cx = s_cxx + buf * CTILE;
        const int cbase = c0 + tile * CTILE;

        for (int j = 0; j < CTILE; ++j) {
            const ulonglong2* row = tb + j * 16;   // uniform broadcast LDS.128
            u64 a0 = 0, a1 = 0, a2 = 0, a3 = 0;
#pragma unroll
            for (int i = 0; i < 8; ++i) {
                ulonglong2 u = row[2 * i];
                ulonglong2 w = row[2 * i + 1];
                a0 = fma2(qv[4 * i + 0], u.x, a0);
                a1 = fma2(qv[4 * i + 1], u.y, a1);
                a2 = fma2(qv[4 * i + 2], w.x, a2);
                a3 = fma2(qv[4 * i + 3], w.y, a3);
            }
            float s = psum(add2(add2(a0, a1), add2(a2, a3)));
            float qc = qxx + cx[j];
            float d = fmaf(2.f, s, -qc);           // exact fp32 neg sq dist
            if (d > thr) {                          // rare
                int jj = cbase + j;
                int p = 15;
                while (p > 0 && mv[p - 1] < d) {   // ties keep earlier (lower) index
                    mv[p] = mv[p - 1];
                    mi[p] = mi[p - 1];
                    --p;
                }
                mv[p] = d;
                mi[p] = jj;
                thr = mv[15];
            }
        }
        __syncthreads();                    // done with buf before overwrite
    }

    float* pv = g_pval + (((size_t)(b * CH + ch)) * N_ + q) * 16;
    int*   pi = g_pidx + (((size_t)(b * CH + ch)) * N_ + q) * 16;
#pragma unroll
    for (int i = 0; i < 16; ++i) { pv[i] = mv[i]; pi[i] = mi[i]; }
}

// ---------------- kernel 2b: 4-way merge of partial top-16 lists ----------------
__global__ void __launch_bounds__(256) merge_kernel() {
    int id = blockIdx.x * 256 + threadIdx.x;       // 0 .. B*N-1
    int b = id >> 13;
    int q = id & (N_ - 1);

    const float* pv[CH];
    const int*   pi[CH];
    float hv[CH];
    int   hx[CH];
    int   cur[CH];
#pragma unroll
    for (int c = 0; c < CH; ++c) {
        pv[c] = g_pval + (((size_t)(b * CH + c)) * N_ + q) * 16;
        pi[c] = g_pidx + (((size_t)(b * CH + c)) * N_ + q) * 16;
        hv[c] = pv[c][0];
        hx[c] = pi[c][0];
        cur[c] = 0;
    }
    int* og = g_knn + (size_t)id * K_;
#pragma unroll
    for (int s = 0; s < 16; ++s) {
        int best = 0;
#pragma unroll
        for (int c = 1; c < CH; ++c)
            if (hv[c] > hv[best] || (hv[c] == hv[best] && hx[c] < hx[best])) best = c;
        og[s] = hx[best];
        if (++cur[best] < 16) {
            hv[best] = pv[best][cur[best]];
            hx[best] = pi[best][cur[best]];
        } else {
            hv[best] = -3.4e38f;
            hx[best] = 0x7fffffff;
        }
    }
}

// ---------------- kernel 3: edge conv + max pool ----------------
#define CT  128   // threads = output channels
#define PPB 64    // points per block

__device__ __forceinline__ void cv_issue(const float* fb, const int* s_nidx,
                                         int p0, int pl, int t,
                                         float4* rn, float4* rx) {
#pragma unroll
    for (int s = 0; s < 3; ++s) {
        if (s == 2 && t >= 16) continue;
        int cid = t + s * CT;
        int r = cid >> 4, c4 = cid & 15;
        const float4* xrow = reinterpret_cast<const float4*>(fb + (size_t)(p0 + pl) * C_);
        if (r < 16) {
            int nj = s_nidx[pl * K_ + r];
            rn[s] = reinterpret_cast<const float4*>(fb + (size_t)nj * C_)[c4];
            rx[s] = xrow[c4];
        } else {
            rn[s] = xrow[c4];
        }
    }
}

__device__ __forceinline__ void cv_commit(float4* buf, int t,
                                          const float4* rn, const float4* rx) {
#pragma unroll
    for (int s = 0; s < 3; ++s) {
        if (s == 2 && t >= 16) continue;
        int cid = t + s * CT;
        int r = cid >> 4, c4 = cid & 15;
        float4 v = rn[s];
        if (r < 16) { v.x -= rx[s].x; v.y -= rx[s].y; v.z -= rx[s].z; v.w -= rx[s].w; }
        buf[r * 16 + c4] = v;
    }
}

__global__ void __launch_bounds__(CT) conv_kernel(const float* __restrict__ W,
                                                  const float* __restrict__ bias,
                                                  float* __restrict__ out) {
    __shared__ float4 sbuf[2][17 * 16];
    __shared__ int s_nidx[PPB * K_];

    int b = blockIdx.y;
    int p0 = blockIdx.x * PPB;
    int t = threadIdx.x;
    const float* fb = g_feats + (size_t)b * N_ * C_;

    u64 w2[64];
    {
        const u64* wp = reinterpret_cast<const u64*>(W + (size_t)t * 2 * C_);
#pragma unroll
        for (int i = 0; i < 64; ++i) w2[i] = wp[i];
    }
    float bo = bias[t];

    for (int i = t; i < PPB * K_; i += CT)
        s_nidx[i] = g_knn[(size_t)(b * N_ + p0) * K_ + i];
    __syncthreads();

    float4 rn[3], rx[3];
    cv_issue(fb, s_nidx, p0, 0, t, rn, rx);

    for (int pl = 0; pl < PPB; ++pl) {
        float4* buf = sbuf[pl & 1];
        cv_commit(buf, t, rn, rx);
        __syncthreads();
        if (pl + 1 < PPB) cv_issue(fb, s_nidx, p0, pl + 1, t, rn, rx);

        const ulonglong2* base = reinterpret_cast<const ulonglong2*>(buf);

        u64 a0 = 0, a1 = 0;
#pragma unroll
        for (int i = 0; i < 16; ++i) {
            ulonglong2 u = base[16 * 16 + i];
            a0 = fma2(w2[2 * i], u.x, a0);
            a1 = fma2(w2[2 * i + 1], u.y, a1);
        }
        float aterm = psum(add2(a0, a1));

        float m = -3.4e38f;
#pragma unroll
        for (int k = 0; k < 16; ++k) {
            u64 c0 = 0, c1 = 0;
#pragma unroll
            for (int i = 0; i < 16; ++i) {
                ulonglong2 u = base[k * 16 + i];
                c0 = fma2(w2[32 + 2 * i], u.x, c0);
                c1 = fma2(w2[33 + 2 * i], u.y, c1);
            }
            float tk = psum(add2(c0, c1));
            m = fmaxf(m, tk);
        }

        out[(size_t)(b * O_ + t) * N_ + p0 + pl] = aterm + m + bo;
    }
}

// ---------------- launch ----------------
extern "C" void kernel_launch(void* const* d_in, const int* in_sizes, int n_in,
                              void* d_out, int out_size) {
    (void)in_sizes; (void)n_in; (void)out_size;
    const float* x    = (const float*)d_in[0];   // (4, 64, 8192, 1)
    const float* W    = (const float*)d_in[1];   // (128, 128)
    const float* bias = (const float*)d_in[2];   // (128,)
    float* out = (float*)d_out;                  // (4, 128, 8192, 1)

    cudaFuncSetAttribute(knn_kernel, cudaFuncAttributeMaxDynamicSharedMemorySize, KNN_SMEM);

    prep_kernel<<<(B_ * N_) / 256, 256>>>(x);
    knn_kernel<<<dim3(N_ / QT, CH, B_), QT, KNN_SMEM>>>();
    merge_kernel<<<(B_ * N_) / 256, 256>>>();
    conv_kernel<<<dim3(N_ / PPB, B_), CT>>>(W, bias, out);
}

// round 6
// speedup vs baseline: 1.5016x; 1.2574x over previous
#include <cuda_runtime.h>
#include <cuda_bf16.h>
#include <cstdint>

#define B_ 4
#define N_ 8192
#define C_ 64
#define K_ 16
#define O_ 128

#define CH 2                       // candidate chunks per query (256 CTAs = 1 wave @ occ 2)
#define QT 256                     // threads = queries per CTA
#define CTILE 128                  // candidates per smem tile
#define CCHUNK (N_ / CH)           // 4096
#define NTILES (CCHUNK / CTILE)    // 32

// ---------------- scratch (no allocs allowed) ----------------
__device__ __align__(16) float g_feats[B_ * N_ * C_];
__device__ __align__(16) float g_xx[B_ * N_];
__device__ __align__(16) int   g_knn[B_ * N_ * K_];
__device__ __align__(16) float g_pval[B_ * CH * N_ * K_];   // partial top-16 values
__device__ __align__(16) int   g_pidx[B_ * CH * N_ * K_];   // partial top-16 indices

typedef unsigned long long u64;

// ---------------- packed f32x2 helpers (sm_103a) ----------------
__device__ __forceinline__ u64 fma2(u64 a, u64 b, u64 c) {
    u64 d;
    asm("fma.rn.f32x2 %0, %1, %2, %3;" : "=l"(d) : "l"(a), "l"(b), "l"(c));
    return d;
}
__device__ __forceinline__ u64 add2(u64 a, u64 b) {
    u64 d;
    asm("add.rn.f32x2 %0, %1, %2;" : "=l"(d) : "l"(a), "l"(b));
    return d;
}
__device__ __forceinline__ float psum(u64 v) {
    return __uint_as_float((unsigned)v) + __uint_as_float((unsigned)(v >> 32));
}
__device__ __forceinline__ uint32_t smem_u32(const void* p) {
    uint32_t a;
    asm("{ .reg .u64 t; cvta.to.shared.u64 t, %1; cvt.u32.u64 %0, t; }" : "=r"(a) : "l"(p));
    return a;
}
__device__ __forceinline__ void cp_async16(uint32_t dst, const void* src) {
    asm volatile("cp.async.cg.shared.global [%0], [%1], 16;" :: "r"(dst), "l"(src) : "memory");
}
__device__ __forceinline__ void cp_commit() {
    asm volatile("cp.async.commit_group;" ::: "memory");
}
__device__ __forceinline__ void cp_wait1() {
    asm volatile("cp.async.wait_group 1;" ::: "memory");
}
__device__ __forceinline__ void cp_wait0() {
    asm volatile("cp.async.wait_group 0;" ::: "memory");
}

// ---------------- kernel 1: transpose x -> feats, compute ||x||^2 ----------------
__global__ void __launch_bounds__(256) prep_kernel(const float* __restrict__ x) {
    int idx = blockIdx.x * 256 + threadIdx.x;      // 0 .. B*N-1
    int b = idx >> 13;
    int n = idx & (N_ - 1);
    const float* xb = x + (size_t)b * C_ * N_ + n;
    float v[C_];
    float acc = 0.f;
#pragma unroll
    for (int c = 0; c < C_; ++c) {
        float t = xb[(size_t)c * N_];              // coalesced across threads
        v[c] = t;
        acc = fmaf(t, t, acc);
    }
    float4* fp = reinterpret_cast<float4*>(g_feats + (size_t)idx * C_);
#pragma unroll
    for (int i = 0; i < C_ / 4; ++i)
        fp[i] = make_float4(v[4 * i], v[4 * i + 1], v[4 * i + 2], v[4 * i + 3]);
    g_xx[idx] = acc;
}

// ---------------- kernel 2: exact fp32 KNN, branch-minimized FFMA2 core ----------------
// Grid (32, CH, B_): 256 queries x CCHUNK candidates per CTA.
// smem layout (bytes):
#define KS_TILE 0                         // 2 x 32768 candidate tiles
#define KS_CXX  65536                     // 2 x 128 floats
#define KS_MV   66560                     // 256 x 16 fp32
#define KS_MI   82944                     // 256 x 16 int
#define KNN_SMEM 99328

__global__ void __launch_bounds__(QT, 2) knn_kernel() {
    extern __shared__ char smem[];
    uint32_t sb = smem_u32(smem);
    const int t = threadIdx.x;
    const int b = blockIdx.z;
    const int ch = blockIdx.y;
    const int q = blockIdx.x * QT + t;
    const int c0 = ch * CCHUNK;

    const float* fb = g_feats + (size_t)b * N_ * C_;
    const float* xxb = g_xx + b * N_;

    float* s_cxx = reinterpret_cast<float*>(smem + KS_CXX);
    float* mv = reinterpret_cast<float*>(smem + KS_MV) + t * 16;
    int*   mi = reinterpret_cast<int*>(smem + KS_MI) + t * 16;

    // query row in registers (64 regs)
    u64 qv[32];
    {
        const u64* qp = reinterpret_cast<const u64*>(fb + (size_t)q * C_);
#pragma unroll
        for (int i = 0; i < 32; ++i) qv[i] = qp[i];
    }
    const float qxx = xxb[q];
#pragma unroll
    for (int i = 0; i < 16; ++i) { mv[i] = -3.4e38f; mi[i] = 0; }
    float thr = -3.4e38f;

    // cp.async tile loader: 128 rows x 256 B = 2048 x 16B chunks, 8 per thread
    auto issue = [&](int tile, int buf) {
        const char* src = reinterpret_cast<const char*>(fb + (size_t)(c0 + tile * CTILE) * C_);
        uint32_t dst = sb + KS_TILE + buf * 32768;
#pragma unroll
        for (int i = 0; i < 8; ++i) {
            int chunk = t + i * QT;
            cp_async16(dst + chunk * 16, src + (size_t)chunk * 16);
        }
        cp_commit();
        if (t < CTILE) s_cxx[buf * CTILE + t] = xxb[c0 + tile * CTILE + t];
    };
    issue(0, 0);

    for (int tile = 0; tile < NTILES; ++tile) {
        const int buf = tile & 1;
        if (tile + 1 < NTILES) { issue(tile + 1, buf ^ 1); cp_wait1(); }
        else                   { cp_wait0(); }
        __syncthreads();                    // tile + cxx visible

        const ulonglong2* tb = reinterpret_cast<const ulonglong2*>(smem + KS_TILE + buf * 32768);
        const float* cx = s_cxx + buf * CTILE;
        const int cbase = c0 + tile * CTILE;

#pragma unroll 1
        for (int jb = 0; jb < CTILE / 8; ++jb) {
            const int j0 = jb * 8;
            const ulonglong2* rows = tb + j0 * 16;    // 8 rows x 16 u2 each

            // 8 independent accumulation chains (branch-free FFMA2 stream)
            u64 acc[8];
#pragma unroll
            for (int c = 0; c < 8; ++c) acc[c] = 0;
#pragma unroll
            for (int i = 0; i < 16; ++i) {
#pragma unroll
                for (int c = 0; c < 8; ++c) {
                    ulonglong2 u = rows[c * 16 + i];   // broadcast LDS.128
                    acc[c] = fma2(qv[2 * i + 1], u.y, fma2(qv[2 * i], u.x, acc[c]));
                }
            }

            float d[8];
            float dmax = -3.4e38f;
#pragma unroll
            for (int c = 0; c < 8; ++c) {
                float s = psum(acc[c]);
                float qc = qxx + cx[j0 + c];
                d[c] = fmaf(2.f, s, -qc);              // exact fp32 neg sq dist
                dmax = fmaxf(dmax, d[c]);
            }

            if (dmax > thr) {                          // one divergence region per 8 candidates
#pragma unroll
                for (int c = 0; c < 8; ++c) {
                    float dv = d[c];
                    if (dv > thr) {
                        int jj = cbase + j0 + c;
                        int p = 15;
                        while (p > 0 && mv[p - 1] < dv) {   // ties keep earlier (lower) index
                            mv[p] = mv[p - 1];
                            mi[p] = mi[p - 1];
                            --p;
                        }
                        mv[p] = dv;
                        mi[p] = jj;
                        thr = mv[15];
                    }
                }
            }
        }
        __syncthreads();                    // done with buf before overwrite
    }

    float* pv = g_pval + (((size_t)(b * CH + ch)) * N_ + q) * 16;
    int*   pi = g_pidx + (((size_t)(b * CH + ch)) * N_ + q) * 16;
#pragma unroll
    for (int i = 0; i < 16; ++i) { pv[i] = mv[i]; pi[i] = mi[i]; }
}

// ---------------- kernel 2b: CH-way merge of partial top-16 lists ----------------
__global__ void __launch_bounds__(256) merge_kernel() {
    int id = blockIdx.x * 256 + threadIdx.x;       // 0 .. B*N-1
    int b = id >> 13;
    int q = id & (N_ - 1);

    const float* pv[CH];
    const int*   pi[CH];
    float hv[CH];
    int   hx[CH];
    int   cur[CH];
#pragma unroll
    for (int c = 0; c < CH; ++c) {
        pv[c] = g_pval + (((size_t)(b * CH + c)) * N_ + q) * 16;
        pi[c] = g_pidx + (((size_t)(b * CH + c)) * N_ + q) * 16;
        hv[c] = pv[c][0];
        hx[c] = pi[c][0];
        cur[c] = 0;
    }
    int* og = g_knn + (size_t)id * K_;
#pragma unroll
    for (int s = 0; s < 16; ++s) {
        int best = 0;
#pragma unroll
        for (int c = 1; c < CH; ++c)
            if (hv[c] > hv[best] || (hv[c] == hv[best] && hx[c] < hx[best])) best = c;
        og[s] = hx[best];
        if (++cur[best] < 16) {
            hv[best] = pv[best][cur[best]];
            hx[best] = pi[best][cur[best]];
        } else {
            hv[best] = -3.4e38f;
            hx[best] = 0x7fffffff;
        }
    }
}

// ---------------- kernel 3: edge conv + max pool ----------------
#define CT  128   // threads = output channels
#define PPB 64    // points per block

__device__ __forceinline__ void cv_issue(const float* fb, const int* s_nidx,
                                         int p0, int pl, int t,
                                         float4* rn, float4* rx) {
#pragma unroll
    for (int s = 0; s < 3; ++s) {
        if (s == 2 && t >= 16) continue;
        int cid = t + s * CT;
        int r = cid >> 4, c4 = cid & 15;
        const float4* xrow = reinterpret_cast<const float4*>(fb + (size_t)(p0 + pl) * C_);
        if (r < 16) {
            int nj = s_nidx[pl * K_ + r];
            rn[s] = reinterpret_cast<const float4*>(fb + (size_t)nj * C_)[c4];
            rx[s] = xrow[c4];
        } else {
            rn[s] = xrow[c4];
        }
    }
}

__device__ __forceinline__ void cv_commit(float4* buf, int t,
                                          const float4* rn, const float4* rx) {
#pragma unroll
    for (int s = 0; s < 3; ++s) {
        if (s == 2 && t >= 16) continue;
        int cid = t + s * CT;
        int r = cid >> 4, c4 = cid & 15;
        float4 v = rn[s];
        if (r < 16) { v.x -= rx[s].x; v.y -= rx[s].y; v.z -= rx[s].z; v.w -= rx[s].w; }
        buf[r * 16 + c4] = v;
    }
}

__global__ void __launch_bounds__(CT) conv_kernel(const float* __restrict__ W,
                                                  const float* __restrict__ bias,
                                                  float* __restrict__ out) {
    __shared__ float4 sbuf[2][17 * 16];
    __shared__ int s_nidx[PPB * K_];

    int b = blockIdx.y;
    int p0 = blockIdx.x * PPB;
    int t = threadIdx.x;
    const float* fb = g_feats + (size_t)b * N_ * C_;

    u64 w2[64];
    {
        const u64* wp = reinterpret_cast<const u64*>(W + (size_t)t * 2 * C_);
#pragma unroll
        for (int i = 0; i < 64; ++i) w2[i] = wp[i];
    }
    float bo = bias[t];

    for (int i = t; i < PPB * K_; i += CT)
        s_nidx[i] = g_knn[(size_t)(b * N_ + p0) * K_ + i];
    __syncthreads();

    float4 rn[3], rx[3];
    cv_issue(fb, s_nidx, p0, 0, t, rn, rx);

    for (int pl = 0; pl < PPB; ++pl) {
        float4* buf = sbuf[pl & 1];
        cv_commit(buf, t, rn, rx);
        __syncthreads();
        if (pl + 1 < PPB) cv_issue(fb, s_nidx, p0, pl + 1, t, rn, rx);

        const ulonglong2* base = reinterpret_cast<const ulonglong2*>(buf);

        u64 a0 = 0, a1 = 0;
#pragma unroll
        for (int i = 0; i < 16; ++i) {
            ulonglong2 u = base[16 * 16 + i];
            a0 = fma2(w2[2 * i], u.x, a0);
            a1 = fma2(w2[2 * i + 1], u.y, a1);
        }
        float aterm = psum(add2(a0, a1));

        float m = -3.4e38f;
#pragma unroll
        for (int k = 0; k < 16; ++k) {
            u64 c0 = 0, c1 = 0;
#pragma unroll
            for (int i = 0; i < 16; ++i) {
                ulonglong2 u = base[k * 16 + i];
                c0 = fma2(w2[32 + 2 * i], u.x, c0);
                c1 = fma2(w2[33 + 2 * i], u.y, c1);
            }
            float tk = psum(add2(c0, c1));
            m = fmaxf(m, tk);
        }

        out[(size_t)(b * O_ + t) * N_ + p0 + pl] = aterm + m + bo;
    }
}

// ---------------- launch ----------------
extern "C" void kernel_launch(void* const* d_in, const int* in_sizes, int n_in,
                              void* d_out, int out_size) {
    (void)in_sizes; (void)n_in; (void)out_size;
    const float* x    = (const float*)d_in[0];   // (4, 64, 8192, 1)
    const float* W    = (const float*)d_in[1];   // (128, 128)
    const float* bias = (const float*)d_in[2];   // (128,)
    float* out = (float*)d_out;                  // (4, 128, 8192, 1)

    cudaFuncSetAttribute(knn_kernel, cudaFuncAttributeMaxDynamicSharedMemorySize, KNN_SMEM);

    prep_kernel<<<(B_ * N_) / 256, 256>>>(x);
    knn_kernel<<<dim3(N_ / QT, CH, B_), QT, KNN_SMEM>>>();
    merge_kernel<<<(B_ * N_) / 256, 256>>>();
    conv_kernel<<<dim3(N_ / PPB, B_), CT>>>(W, bias, out);
}